// round 4
// baseline (speedup 1.0000x reference)
#include <cuda_runtime.h>
#include <cuda_bf16.h>
#include <cstdint>

#define B_SZ 8192
#define D_SZ 256

// ---------------- device scratch ----------------
__device__ unsigned short g_Anb[B_SZ * D_SZ];   // normalized audio, bf16
__device__ unsigned short g_Tnb[B_SZ * D_SZ];   // normalized text, bf16
__device__ unsigned g_rowmax[B_SZ];
__device__ unsigned g_colmax[B_SZ];
__device__ float    g_diag[B_SZ];               // exact fp32 diag
__device__ float    g_partial[32];

// Order-preserving float<->uint encoding for atomicMax on floats.
__device__ __forceinline__ unsigned fenc(float f) {
    unsigned u = __float_as_uint(f);
    return (u & 0x80000000u) ? ~u : (u | 0x80000000u);
}
__device__ __forceinline__ float fdec(unsigned u) {
    return (u & 0x80000000u) ? __uint_as_float(u ^ 0x80000000u) : __uint_as_float(~u);
}

// ---------------- normalize + bf16 convert (1 warp / row) ----------------
__global__ void normalize_kernel(const float* __restrict__ A,
                                 const float* __restrict__ T) {
    int row  = blockIdx.x * blockDim.y + threadIdx.y;   // 0 .. 2B-1
    int lane = threadIdx.x;
    const float* src;
    unsigned short* dst;
    if (row < B_SZ) { src = A + (size_t)row * D_SZ;          dst = g_Anb + (size_t)row * D_SZ; }
    else            { src = T + (size_t)(row - B_SZ) * D_SZ; dst = g_Tnb + (size_t)(row - B_SZ) * D_SZ; }

    float4 v0 = ((const float4*)src)[2 * lane];
    float4 v1 = ((const float4*)src)[2 * lane + 1];
    float ss = v0.x*v0.x + v0.y*v0.y + v0.z*v0.z + v0.w*v0.w
             + v1.x*v1.x + v1.y*v1.y + v1.z*v1.z + v1.w*v1.w;
    #pragma unroll
    for (int o = 16; o > 0; o >>= 1) ss += __shfl_xor_sync(0xffffffffu, ss, o);
    float inv = 1.0f / sqrtf(ss);

    __nv_bfloat162 b0 = __floats2bfloat162_rn(v0.x * inv, v0.y * inv);
    __nv_bfloat162 b1 = __floats2bfloat162_rn(v0.z * inv, v0.w * inv);
    __nv_bfloat162 b2 = __floats2bfloat162_rn(v1.x * inv, v1.y * inv);
    __nv_bfloat162 b3 = __floats2bfloat162_rn(v1.z * inv, v1.w * inv);
    uint4 o4;
    o4.x = *(unsigned*)&b0; o4.y = *(unsigned*)&b1;
    o4.z = *(unsigned*)&b2; o4.w = *(unsigned*)&b3;
    *(uint4*)(dst + lane * 8) = o4;
}

// ---------------- exact fp32 diag + rowmax/colmax init ----------------
__global__ void diag_kernel(const float* __restrict__ A,
                            const float* __restrict__ T) {
    // fold sentinel init in (grid covers 8192 rows; 1024 blocks x 256 thr)
    int g = blockIdx.x * 256 + threadIdx.x;
    if (g < B_SZ) {
        unsigned s = fenc(-3e38f);
        g_rowmax[g] = s;
        g_colmax[g] = s;
    }

    int row  = blockIdx.x * blockDim.y + threadIdx.y;
    int lane = threadIdx.x;
    const float* a = A + (size_t)row * D_SZ;
    const float* t = T + (size_t)row * D_SZ;
    float4 a0 = ((const float4*)a)[2 * lane];
    float4 a1 = ((const float4*)a)[2 * lane + 1];
    float4 t0 = ((const float4*)t)[2 * lane];
    float4 t1 = ((const float4*)t)[2 * lane + 1];
    float sa = a0.x*a0.x + a0.y*a0.y + a0.z*a0.z + a0.w*a0.w
             + a1.x*a1.x + a1.y*a1.y + a1.z*a1.z + a1.w*a1.w;
    float st = t0.x*t0.x + t0.y*t0.y + t0.z*t0.z + t0.w*t0.w
             + t1.x*t1.x + t1.y*t1.y + t1.z*t1.z + t1.w*t1.w;
    float dt = a0.x*t0.x + a0.y*t0.y + a0.z*t0.z + a0.w*t0.w
             + a1.x*t1.x + a1.y*t1.y + a1.z*t1.z + a1.w*t1.w;
    #pragma unroll
    for (int o = 16; o > 0; o >>= 1) {
        sa += __shfl_xor_sync(0xffffffffu, sa, o);
        st += __shfl_xor_sync(0xffffffffu, st, o);
        dt += __shfl_xor_sync(0xffffffffu, dt, o);
    }
    if (lane == 0) g_diag[row] = dt / (sqrtf(sa) * sqrtf(st));
}

// ---------------- warp-MMA GEMM + masked row/col max ----------------
// CTA tile BM=128 x BN=256, BK=32, 256 threads, 8 warps (2x4), 64x64 per warp.
// 3-stage cp.async pipeline, one __syncthreads per k-tile.
// Smem row = 64B (one k-slab of 32 bf16), swizzle grp ^= (row>>1)&3.

#define BM 128
#define BN 256
#define BK 32
#define NSTG 3
#define A_BYTES  (BM * BK * 2)           // 8192
#define B_BYTES  (BN * BK * 2)           // 16384
#define STG_BYTES (A_BYTES + B_BYTES)    // 24576
#define SM_LABR  (NSTG * STG_BYTES)            // 73728, 128*8
#define SM_LABC  (SM_LABR + 1024)               // 256*8
#define SM_RMAX  (SM_LABC + 2048)               // 128*4
#define SM_CMAX  (SM_RMAX + 512)                // 256*4
#define DYN_SMEM (SM_CMAX + 1024)               // 78336

__device__ __forceinline__ void cp_async16(uint32_t saddr, const void* gaddr) {
    asm volatile("cp.async.cg.shared.global [%0], [%1], 16;" :: "r"(saddr), "l"(gaddr));
}
__device__ __forceinline__ void ldm_x4(uint32_t (&r)[4], uint32_t addr) {
    asm volatile("ldmatrix.sync.aligned.m8n8.x4.shared.b16 {%0,%1,%2,%3}, [%4];"
                 : "=r"(r[0]), "=r"(r[1]), "=r"(r[2]), "=r"(r[3]) : "r"(addr));
}
__device__ __forceinline__ void mma_bf16(float (&c)[4], const uint32_t (&a)[4],
                                         uint32_t b0, uint32_t b1) {
    asm volatile("mma.sync.aligned.m16n8k16.row.col.f32.bf16.bf16.f32 "
                 "{%0,%1,%2,%3}, {%4,%5,%6,%7}, {%8,%9}, {%0,%1,%2,%3};"
                 : "+f"(c[0]), "+f"(c[1]), "+f"(c[2]), "+f"(c[3])
                 : "r"(a[0]), "r"(a[1]), "r"(a[2]), "r"(a[3]), "r"(b0), "r"(b1));
}

__global__ void __launch_bounds__(256, 1)
gemm_max_kernel(const long long* __restrict__ labels) {
    extern __shared__ __align__(1024) char sm[];

    const int tid  = threadIdx.x;
    const int w    = tid >> 5;
    const int lane = tid & 31;
    const int wm   = w >> 2;        // 0..1  -> 64-row band
    const int wn   = w & 3;         // 0..3  -> 64-col band
    const int bx   = blockIdx.x;    // N tile (text, 256 cols)
    const int by   = blockIdx.y;    // M tile (audio, 128 rows)

    long long* sLr = (long long*)(sm + SM_LABR);
    long long* sLc = (long long*)(sm + SM_LABC);
    unsigned*  s_rmax = (unsigned*)(sm + SM_RMAX);
    unsigned*  s_cmax = (unsigned*)(sm + SM_CMAX);

    {
        unsigned s = fenc(-3e38f);
        if (tid < 128) { s_rmax[tid] = s; sLr[tid] = labels[by * 128 + tid]; }
        s_cmax[tid] = s;
        sLc[tid] = labels[bx * 256 + tid];
    }

    float acc[4][8][4];
    #pragma unroll
    for (int i = 0; i < 4; i++)
        #pragma unroll
        for (int j = 0; j < 8; j++)
            #pragma unroll
            for (int e = 0; e < 4; e++) acc[i][j][e] = 0.0f;

    const unsigned short* Ag = g_Anb + (size_t)(by * 128) * D_SZ;
    const unsigned short* Bg = g_Tnb + (size_t)(bx * 256) * D_SZ;
    const uint32_t smb = (uint32_t)__cvta_generic_to_shared(sm);

    auto swz = [](int row, int grp) -> int {
        return row * 64 + ((grp ^ ((row >> 1) & 3)) << 4);
    };

    // stage loader: A = 512 16B-chunks (2/thread), B = 1024 (4/thread)
    auto load_stage = [&](int st, int kt) {
        int kofs = kt * BK;
        uint32_t sa = smb + st * STG_BYTES;
        uint32_t sb = sa + A_BYTES;
        #pragma unroll
        for (int p = 0; p < 2; ++p) {
            int c = p * 256 + tid;
            int row = c >> 2, grp = c & 3;
            cp_async16(sa + swz(row, grp), Ag + (size_t)row * D_SZ + kofs + grp * 8);
        }
        #pragma unroll
        for (int p = 0; p < 4; ++p) {
            int c = p * 256 + tid;
            int row = c >> 2, grp = c & 3;
            cp_async16(sb + swz(row, grp), Bg + (size_t)row * D_SZ + kofs + grp * 8);
        }
    };

    load_stage(0, 0);
    asm volatile("cp.async.commit_group;");
    load_stage(1, 1);
    asm volatile("cp.async.commit_group;");

    const int lrow = lane & 15;
    const int lhi  = lane >> 4;

    #pragma unroll
    for (int kt = 0; kt < 8; ++kt) {
        asm volatile("cp.async.wait_group 1;");
        __syncthreads();

        const int s = kt % NSTG;
        const uint32_t sa = smb + s * STG_BYTES;
        const uint32_t sb = sa + A_BYTES;

        #pragma unroll
        for (int ks = 0; ks < 2; ++ks) {
            const int grp = ks * 2 + lhi;
            uint32_t a[4][4];
            #pragma unroll
            for (int mf = 0; mf < 4; ++mf) {
                int row = wm * 64 + mf * 16 + lrow;
                ldm_x4(a[mf], sa + swz(row, grp));
            }
            uint32_t b[8][2];
            #pragma unroll
            for (int np = 0; np < 4; ++np) {
                int row = wn * 64 + np * 16 + lrow;
                uint32_t r[4];
                ldm_x4(r, sb + swz(row, grp));
                b[np * 2 + 0][0] = r[0];
                b[np * 2 + 1][0] = r[1];
                b[np * 2 + 0][1] = r[2];
                b[np * 2 + 1][1] = r[3];
            }
            #pragma unroll
            for (int mf = 0; mf < 4; ++mf)
                #pragma unroll
                for (int nb = 0; nb < 8; ++nb)
                    mma_bf16(acc[mf][nb], a[mf], b[nb][0], b[nb][1]);
        }

        if (kt < 6) load_stage((kt + 2) % NSTG, kt + 2);
        asm volatile("cp.async.commit_group;");
    }

    // ---- epilogue: masked row/col max ----
    const int qr = lane >> 2;        // 0..7
    const int qc = (lane & 3) * 2;   // 0,2,4,6

    #pragma unroll
    for (int mf = 0; mf < 4; ++mf) {
        #pragma unroll
        for (int h = 0; h < 2; ++h) {
            int rloc = wm * 64 + mf * 16 + qr + h * 8;
            long long labR = sLr[rloc];
            float rm = -3e38f;
            #pragma unroll
            for (int nb = 0; nb < 8; ++nb) {
                int cl = wn * 64 + nb * 8 + qc;
                float v0 = acc[mf][nb][h * 2 + 0];
                float v1 = acc[mf][nb][h * 2 + 1];
                if (labR != sLc[cl])     rm = fmaxf(rm, v0);
                if (labR != sLc[cl + 1]) rm = fmaxf(rm, v1);
            }
            atomicMax(&s_rmax[rloc], fenc(rm));
        }
    }
    #pragma unroll
    for (int nb = 0; nb < 8; ++nb) {
        int cl = wn * 64 + nb * 8 + qc;
        long long lc0 = sLc[cl], lc1 = sLc[cl + 1];
        float cm0 = -3e38f, cm1 = -3e38f;
        #pragma unroll
        for (int mf = 0; mf < 4; ++mf) {
            #pragma unroll
            for (int h = 0; h < 2; ++h) {
                int rloc = wm * 64 + mf * 16 + qr + h * 8;
                long long labR = sLr[rloc];
                float v0 = acc[mf][nb][h * 2 + 0];
                float v1 = acc[mf][nb][h * 2 + 1];
                if (labR != lc0) cm0 = fmaxf(cm0, v0);
                if (labR != lc1) cm1 = fmaxf(cm1, v1);
            }
        }
        atomicMax(&s_cmax[cl],     fenc(cm0));
        atomicMax(&s_cmax[cl + 1], fenc(cm1));
    }

    __syncthreads();
    if (tid < 128) atomicMax(&g_rowmax[by * 128 + tid], s_rmax[tid]);
    atomicMax(&g_colmax[bx * 256 + tid], s_cmax[tid]);
}

// ---------------- loss + reduction ----------------
__device__ __forceinline__ float loss_term(float d, float m) {
    bool valid = (d < 1.0f - 1e-5f) && (m + 0.2f > d);
    if (!valid) return 0.0f;
    float pl = fmaxf(0.2f * d * d - 0.7f * d + 0.5f, 0.0f);
    float nl = fmaxf(0.9f * m * m - 0.4f * m + 0.03f, 0.0f);
    return pl + nl;
}

__global__ void loss_kernel() {
    __shared__ float sdata[256];
    int i = blockIdx.x * 256 + threadIdx.x;
    float d  = g_diag[i];
    float mr = fdec(g_rowmax[i]);
    float mc = fdec(g_colmax[i]);
    float c  = loss_term(d, mr) + loss_term(d, mc);
    sdata[threadIdx.x] = c;
    __syncthreads();
    #pragma unroll
    for (int s = 128; s > 0; s >>= 1) {
        if (threadIdx.x < s) sdata[threadIdx.x] += sdata[threadIdx.x + s];
        __syncthreads();
    }
    if (threadIdx.x == 0) g_partial[blockIdx.x] = sdata[0];
}

__global__ void final_kernel(float* __restrict__ out) {
    float s = (threadIdx.x < 32) ? g_partial[threadIdx.x] : 0.0f;
    #pragma unroll
    for (int o = 16; o > 0; o >>= 1) s += __shfl_xor_sync(0xffffffffu, s, o);
    if (threadIdx.x == 0) out[0] = s / (float)B_SZ;
}

// ---------------- launch ----------------
extern "C" void kernel_launch(void* const* d_in, const int* in_sizes, int n_in,
                              void* d_out, int out_size) {
    const float*     A      = (const float*)d_in[0];
    const float*     T      = (const float*)d_in[1];
    const long long* labels = (const long long*)d_in[2];
    float*           out    = (float*)d_out;

    cudaFuncSetAttribute(gemm_max_kernel,
                         cudaFuncAttributeMaxDynamicSharedMemorySize, DYN_SMEM);

    normalize_kernel<<<(2 * B_SZ) / 8, dim3(32, 8)>>>(A, T);
    diag_kernel<<<B_SZ / 8, dim3(32, 8)>>>(A, T);
    gemm_max_kernel<<<dim3(B_SZ / 256, B_SZ / 128), 256, DYN_SMEM>>>(labels);
    loss_kernel<<<B_SZ / 256, 256>>>();
    final_kernel<<<1, 32>>>(out);
}

// round 5
// speedup vs baseline: 1.3149x; 1.3149x over previous
#include <cuda_runtime.h>
#include <cuda_bf16.h>
#include <cstdint>

#define B_SZ 8192
#define D_SZ 256

// ---------------- device scratch ----------------
__device__ unsigned short g_Anb[B_SZ * D_SZ];   // normalized audio, bf16
__device__ unsigned short g_Tnb[B_SZ * D_SZ];   // normalized text, bf16
__device__ unsigned g_rowmax[B_SZ];
__device__ unsigned g_colmax[B_SZ];
__device__ float    g_diag[B_SZ];               // exact fp32 diag
__device__ float    g_partial[32];

// Order-preserving float<->uint encoding for atomicMax on floats.
__device__ __forceinline__ unsigned fenc(float f) {
    unsigned u = __float_as_uint(f);
    return (u & 0x80000000u) ? ~u : (u | 0x80000000u);
}
__device__ __forceinline__ float fdec(unsigned u) {
    return (u & 0x80000000u) ? __uint_as_float(u ^ 0x80000000u) : __uint_as_float(~u);
}

// ---------------- normalize + bf16 convert (1 warp / row) ----------------
__global__ void normalize_kernel(const float* __restrict__ A,
                                 const float* __restrict__ T) {
    int row  = blockIdx.x * blockDim.y + threadIdx.y;   // 0 .. 2B-1
    int lane = threadIdx.x;
    const float* src;
    unsigned short* dst;
    if (row < B_SZ) { src = A + (size_t)row * D_SZ;          dst = g_Anb + (size_t)row * D_SZ; }
    else            { src = T + (size_t)(row - B_SZ) * D_SZ; dst = g_Tnb + (size_t)(row - B_SZ) * D_SZ; }

    float4 v0 = ((const float4*)src)[2 * lane];
    float4 v1 = ((const float4*)src)[2 * lane + 1];
    float ss = v0.x*v0.x + v0.y*v0.y + v0.z*v0.z + v0.w*v0.w
             + v1.x*v1.x + v1.y*v1.y + v1.z*v1.z + v1.w*v1.w;
    #pragma unroll
    for (int o = 16; o > 0; o >>= 1) ss += __shfl_xor_sync(0xffffffffu, ss, o);
    float inv = 1.0f / sqrtf(ss);

    __nv_bfloat162 b0 = __floats2bfloat162_rn(v0.x * inv, v0.y * inv);
    __nv_bfloat162 b1 = __floats2bfloat162_rn(v0.z * inv, v0.w * inv);
    __nv_bfloat162 b2 = __floats2bfloat162_rn(v1.x * inv, v1.y * inv);
    __nv_bfloat162 b3 = __floats2bfloat162_rn(v1.z * inv, v1.w * inv);
    uint4 o4;
    o4.x = *(unsigned*)&b0; o4.y = *(unsigned*)&b1;
    o4.z = *(unsigned*)&b2; o4.w = *(unsigned*)&b3;
    *(uint4*)(dst + lane * 8) = o4;
}

// ---------------- exact fp32 diag + rowmax/colmax init ----------------
__global__ void diag_kernel(const float* __restrict__ A,
                            const float* __restrict__ T) {
    int g = blockIdx.x * 256 + threadIdx.x;
    if (g < B_SZ) {
        unsigned s = fenc(-3e38f);
        g_rowmax[g] = s;
        g_colmax[g] = s;
    }

    int row  = blockIdx.x * blockDim.y + threadIdx.y;
    int lane = threadIdx.x;
    const float* a = A + (size_t)row * D_SZ;
    const float* t = T + (size_t)row * D_SZ;
    float4 a0 = ((const float4*)a)[2 * lane];
    float4 a1 = ((const float4*)a)[2 * lane + 1];
    float4 t0 = ((const float4*)t)[2 * lane];
    float4 t1 = ((const float4*)t)[2 * lane + 1];
    float sa = a0.x*a0.x + a0.y*a0.y + a0.z*a0.z + a0.w*a0.w
             + a1.x*a1.x + a1.y*a1.y + a1.z*a1.z + a1.w*a1.w;
    float st = t0.x*t0.x + t0.y*t0.y + t0.z*t0.z + t0.w*t0.w
             + t1.x*t1.x + t1.y*t1.y + t1.z*t1.z + t1.w*t1.w;
    float dt = a0.x*t0.x + a0.y*t0.y + a0.z*t0.z + a0.w*t0.w
             + a1.x*t1.x + a1.y*t1.y + a1.z*t1.z + a1.w*t1.w;
    #pragma unroll
    for (int o = 16; o > 0; o >>= 1) {
        sa += __shfl_xor_sync(0xffffffffu, sa, o);
        st += __shfl_xor_sync(0xffffffffu, st, o);
        dt += __shfl_xor_sync(0xffffffffu, dt, o);
    }
    if (lane == 0) g_diag[row] = dt / (sqrtf(sa) * sqrtf(st));
}

// ---------------- warp-MMA GEMM + masked row/col max ----------------
// CTA tile 128x128, BK=32, 256 threads (8 warps, 2x4), 64x32 per warp.
// 3-stage cp.async ring, ONE __syncthreads per k-tile, loads before compute.

#define BK 32
#define TILE_BYTES 8192                      // 128 rows x 64B
#define STG_BYTES  (2 * TILE_BYTES)          // A + B per stage
#define NSTG 3
#define SM_LABR  (NSTG * STG_BYTES)          // 49152
#define SM_LABC  (SM_LABR + 1024)
#define SM_RMAX  (SM_LABC + 1024)
#define SM_CMAX  (SM_RMAX + 512)
#define DYN_SMEM (SM_CMAX + 512)             // 52224

__device__ __forceinline__ void cp_async16(uint32_t saddr, const void* gaddr) {
    asm volatile("cp.async.cg.shared.global [%0], [%1], 16;" :: "r"(saddr), "l"(gaddr));
}
__device__ __forceinline__ void ldm_x4(uint32_t (&r)[4], uint32_t addr) {
    asm volatile("ldmatrix.sync.aligned.m8n8.x4.shared.b16 {%0,%1,%2,%3}, [%4];"
                 : "=r"(r[0]), "=r"(r[1]), "=r"(r[2]), "=r"(r[3]) : "r"(addr));
}
__device__ __forceinline__ void mma_bf16(float (&c)[4], const uint32_t (&a)[4],
                                         uint32_t b0, uint32_t b1) {
    asm volatile("mma.sync.aligned.m16n8k16.row.col.f32.bf16.bf16.f32 "
                 "{%0,%1,%2,%3}, {%4,%5,%6,%7}, {%8,%9}, {%0,%1,%2,%3};"
                 : "+f"(c[0]), "+f"(c[1]), "+f"(c[2]), "+f"(c[3])
                 : "r"(a[0]), "r"(a[1]), "r"(a[2]), "r"(a[3]), "r"(b0), "r"(b1));
}

__global__ void __launch_bounds__(256, 2)
gemm_max_kernel(const long long* __restrict__ labels) {
    extern __shared__ __align__(1024) char sm[];

    const int tid  = threadIdx.x;
    const int w    = tid >> 5;
    const int lane = tid & 31;
    const int wm   = w >> 2;        // 0..1
    const int wn   = w & 3;         // 0..3
    const int bx   = blockIdx.x;    // N tile (text)
    const int by   = blockIdx.y;    // M tile (audio)

    long long* sLr = (long long*)(sm + SM_LABR);
    long long* sLc = (long long*)(sm + SM_LABC);
    unsigned*  s_rmax = (unsigned*)(sm + SM_RMAX);
    unsigned*  s_cmax = (unsigned*)(sm + SM_CMAX);

    if (tid < 128) {
        unsigned s = fenc(-3e38f);
        s_rmax[tid] = s;
        s_cmax[tid] = s;
        sLr[tid] = labels[by * 128 + tid];
        sLc[tid] = labels[bx * 128 + tid];
    }

    float acc[4][4][4];
    #pragma unroll
    for (int i = 0; i < 4; i++)
        #pragma unroll
        for (int j = 0; j < 4; j++)
            #pragma unroll
            for (int e = 0; e < 4; e++) acc[i][j][e] = 0.0f;

    const unsigned short* Ag = g_Anb + (size_t)(by * 128) * D_SZ;
    const unsigned short* Bg = g_Tnb + (size_t)(bx * 128) * D_SZ;
    const uint32_t smb = (uint32_t)__cvta_generic_to_shared(sm);

    auto swz = [](int row, int grp) -> int {
        return row * 64 + ((grp ^ ((row >> 1) & 3)) << 4);
    };

    // one stage = A tile (128x32) + B tile (128x32); 2 chunks each per thread
    auto load_stage = [&](int st, int kt) {
        int kofs = kt * BK;
        uint32_t sa = smb + st * STG_BYTES;
        uint32_t sb = sa + TILE_BYTES;
        #pragma unroll
        for (int p = 0; p < 2; ++p) {
            int c = p * 256 + tid;
            int row = c >> 2, grp = c & 3;
            int so = swz(row, grp);
            const unsigned short* gsrc = Ag + (size_t)row * D_SZ + kofs + grp * 8;
            cp_async16(sa + so, gsrc);
            cp_async16(sb + so, Bg + (size_t)row * D_SZ + kofs + grp * 8);
        }
    };

    load_stage(0, 0);
    asm volatile("cp.async.commit_group;");
    load_stage(1, 1);
    asm volatile("cp.async.commit_group;");

    const int lrow = lane & 15;
    const int lhi  = lane >> 4;

    #pragma unroll
    for (int kt = 0; kt < 8; ++kt) {
        asm volatile("cp.async.wait_group 1;");
        __syncthreads();

        // issue next-next stage loads FIRST so they overlap the MMA block
        if (kt < 6) load_stage((kt + 2) % NSTG, kt + 2);
        asm volatile("cp.async.commit_group;");

        const int s = kt % NSTG;
        const uint32_t sa = smb + s * STG_BYTES;
        const uint32_t sb = sa + TILE_BYTES;

        #pragma unroll
        for (int ks = 0; ks < 2; ++ks) {
            const int grp = ks * 2 + lhi;
            uint32_t a[4][4];
            #pragma unroll
            for (int mf = 0; mf < 4; ++mf) {
                int row = wm * 64 + mf * 16 + lrow;
                ldm_x4(a[mf], sa + swz(row, grp));
            }
            uint32_t b[4][2];
            #pragma unroll
            for (int np = 0; np < 2; ++np) {
                int row = wn * 32 + np * 16 + lrow;
                uint32_t r[4];
                ldm_x4(r, sb + swz(row, grp));
                b[np * 2 + 0][0] = r[0];
                b[np * 2 + 1][0] = r[1];
                b[np * 2 + 0][1] = r[2];
                b[np * 2 + 1][1] = r[3];
            }
            #pragma unroll
            for (int mf = 0; mf < 4; ++mf)
                #pragma unroll
                for (int nf = 0; nf < 4; ++nf)
                    mma_bf16(acc[mf][nf], a[mf], b[nf][0], b[nf][1]);
        }
    }

    // ---- epilogue: masked row/col max ----
    const int qr = lane >> 2;        // 0..7
    const int qc = (lane & 3) * 2;   // 0,2,4,6

    #pragma unroll
    for (int mf = 0; mf < 4; ++mf) {
        #pragma unroll
        for (int h = 0; h < 2; ++h) {
            int rloc = wm * 64 + mf * 16 + qr + h * 8;
            long long labR = sLr[rloc];
            float rm = -3e38f;
            #pragma unroll
            for (int nf = 0; nf < 4; ++nf) {
                int cl = wn * 32 + nf * 8 + qc;
                float v0 = acc[mf][nf][h * 2 + 0];
                float v1 = acc[mf][nf][h * 2 + 1];
                if (labR != sLc[cl])     rm = fmaxf(rm, v0);
                if (labR != sLc[cl + 1]) rm = fmaxf(rm, v1);
            }
            atomicMax(&s_rmax[rloc], fenc(rm));
        }
    }
    #pragma unroll
    for (int nf = 0; nf < 4; ++nf) {
        int cl = wn * 32 + nf * 8 + qc;
        long long lc0 = sLc[cl], lc1 = sLc[cl + 1];
        float cm0 = -3e38f, cm1 = -3e38f;
        #pragma unroll
        for (int mf = 0; mf < 4; ++mf) {
            #pragma unroll
            for (int h = 0; h < 2; ++h) {
                int rloc = wm * 64 + mf * 16 + qr + h * 8;
                long long labR = sLr[rloc];
                float v0 = acc[mf][nf][h * 2 + 0];
                float v1 = acc[mf][nf][h * 2 + 1];
                if (labR != lc0) cm0 = fmaxf(cm0, v0);
                if (labR != lc1) cm1 = fmaxf(cm1, v1);
            }
        }
        atomicMax(&s_cmax[cl],     fenc(cm0));
        atomicMax(&s_cmax[cl + 1], fenc(cm1));
    }

    __syncthreads();
    if (tid < 128) {
        atomicMax(&g_rowmax[by * 128 + tid], s_rmax[tid]);
        atomicMax(&g_colmax[bx * 128 + tid], s_cmax[tid]);
    }
}

// ---------------- loss + reduction ----------------
__device__ __forceinline__ float loss_term(float d, float m) {
    bool valid = (d < 1.0f - 1e-5f) && (m + 0.2f > d);
    if (!valid) return 0.0f;
    float pl = fmaxf(0.2f * d * d - 0.7f * d + 0.5f, 0.0f);
    float nl = fmaxf(0.9f * m * m - 0.4f * m + 0.03f, 0.0f);
    return pl + nl;
}

__global__ void loss_kernel() {
    __shared__ float sdata[256];
    int i = blockIdx.x * 256 + threadIdx.x;
    float d  = g_diag[i];
    float mr = fdec(g_rowmax[i]);
    float mc = fdec(g_colmax[i]);
    float c  = loss_term(d, mr) + loss_term(d, mc);
    sdata[threadIdx.x] = c;
    __syncthreads();
    #pragma unroll
    for (int s = 128; s > 0; s >>= 1) {
        if (threadIdx.x < s) sdata[threadIdx.x] += sdata[threadIdx.x + s];
        __syncthreads();
    }
    if (threadIdx.x == 0) g_partial[blockIdx.x] = sdata[0];
}

__global__ void final_kernel(float* __restrict__ out) {
    float s = (threadIdx.x < 32) ? g_partial[threadIdx.x] : 0.0f;
    #pragma unroll
    for (int o = 16; o > 0; o >>= 1) s += __shfl_xor_sync(0xffffffffu, s, o);
    if (threadIdx.x == 0) out[0] = s / (float)B_SZ;
}

// ---------------- launch ----------------
extern "C" void kernel_launch(void* const* d_in, const int* in_sizes, int n_in,
                              void* d_out, int out_size) {
    const float*     A      = (const float*)d_in[0];
    const float*     T      = (const float*)d_in[1];
    const long long* labels = (const long long*)d_in[2];
    float*           out    = (float*)d_out;

    cudaFuncSetAttribute(gemm_max_kernel,
                         cudaFuncAttributeMaxDynamicSharedMemorySize, DYN_SMEM);

    normalize_kernel<<<(2 * B_SZ) / 8, dim3(32, 8)>>>(A, T);
    diag_kernel<<<B_SZ / 8, dim3(32, 8)>>>(A, T);
    gemm_max_kernel<<<dim3(B_SZ / 128, B_SZ / 128), 256, DYN_SMEM>>>(labels);
    loss_kernel<<<B_SZ / 256, 256>>>();
    final_kernel<<<1, 32>>>(out);
}